// round 3
// baseline (speedup 1.0000x reference)
#include <cuda_runtime.h>
#include <cuda_bf16.h>

// SqRL split: horizontal/corner kernel (coalesced/vector/broadcast loads) +
// masked 32x32 smem transpose for the vertical edge segments.
//
// Ring r (0..255), i = 255-r, el = 2r+1, b1 = 256+r:
//   b2 = 766-r, b3 = 767+r   (right edge, vertical)
//   b4 = 1277-r, b5 = 1278+r (bottom edge)
//   b6 = 1788-r, b7 = 1789+r (left edge, vertical)
// Vertical identities (r-independent j mapping):
//   out[r][511+row]  = x[row][256+r]  for |row-255| <= r
//   out[r][2044-row] = x[row][255-r]  for |row-256| <= r

#define HH  512
#define HR  256
#define RL  2048

__device__ __forceinline__ int sqrl_seg(int jp, int i, int b1, int b2, int b3,
                                        int b4, int b5, int b6, int b7) {
    if (jp < i)  return 0;      // TL corner
    if (jp < b1) return 1;      // top edge
    if (jp < b2) return 2;      // TR corner
    if (jp < b3) return 3;      // right edge (vertical -> skip)
    if (jp < b4) return 4;      // BR corner
    if (jp < b5) return 5;      // bottom edge (reversed)
    if (jp < b6) return 6;      // BL corner
    if (jp < b7) return 7;      // left edge (vertical -> skip)
    return 0;                   // trailing TL corner
}

__global__ __launch_bounds__(256)
void sqrl_horiz(const float* __restrict__ x, float* __restrict__ out) {
    const int r  = blockIdx.y;
    const int bc = blockIdx.z;
    const int i  = (HR - 1) - r;
    const int el = 2 * r + 1;
    const int b1 = i + el;          // 256 + r
    const int b2 = b1 + 2 * i;      // 766 - r
    const int b3 = b2 + el;         // 767 + r
    const int b4 = b3 + 2 * i;      // 1277 - r
    const int b5 = b4 + el;         // 1278 + r
    const int b6 = b5 + 2 * i;      // 1788 - r
    const int b7 = b6 + el;         // 1789 + r

    const int jbase = blockIdx.x * 1024 + threadIdx.x * 4;
    const float* __restrict__ img = x + (size_t)bc * (HH * HH);
    float* __restrict__ orow = out + (((size_t)bc * HR) + (size_t)r) * RL;

    int j0 = jbase;
    if (j0 >= 2044) j0 -= 2044;     // tail wrap block -> copies of cols [0,4)
    const int j3 = j0 + 3;

    const int s0 = sqrl_seg(j0, i, b1, b2, b3, b4, b5, b6, b7);
    if (s0 == sqrl_seg(j3, i, b1, b2, b3, b4, b5, b6, b7)) {
        float4 v;
        switch (s0) {
        case 3: case 7: return;     // vertical: handled by transpose kernel
        case 0: { float c = __ldg(img + i * HH + i);            v = make_float4(c, c, c, c); break; }
        case 2: { float c = __ldg(img + i * HH + (HH - 1 - i)); v = make_float4(c, c, c, c); break; }
        case 4: { float c = __ldg(img + b1 * HH + b1);          v = make_float4(c, c, c, c); break; }
        case 6: { float c = __ldg(img + b1 * HH + i);           v = make_float4(c, c, c, c); break; }
        case 1:   // top edge: cols j0..j0+3, 16B aligned
            v = *reinterpret_cast<const float4*>(img + i * HH + j0);
            break;
        default:  // case 5: bottom edge reversed, cols c0..c0-3; base 8B aligned
        {
            const int clo = b1 - (j0 - b4) - 3;   // = 1530 - j0 (== 2 mod 4 -> 8B aligned)
            const float2 lo = *reinterpret_cast<const float2*>(img + b1 * HH + clo);
            const float2 hi = *reinterpret_cast<const float2*>(img + b1 * HH + clo + 2);
            v = make_float4(hi.y, hi.x, lo.y, lo.x);
            break;
        }
        }
        *reinterpret_cast<float4*>(orow + jbase) = v;
    } else {
        // segment-boundary block: per-element, skipping vertical lanes
        #pragma unroll
        for (int k = 0; k < 4; ++k) {
            const int jp = j0 + k;
            const int s = sqrl_seg(jp, i, b1, b2, b3, b4, b5, b6, b7);
            if (s == 3 || s == 7) continue;
            int row, col;
            switch (s) {
            case 0: row = i;  col = i;               break;
            case 1: row = i;  col = jp;              break;
            case 2: row = i;  col = HH - 1 - i;      break;
            case 4: row = b1; col = b1;              break;
            case 5: row = b1; col = b1 - (jp - b4);  break;
            default: row = b1; col = i;              break; // case 6
            }
            orow[jbase + k] = __ldg(img + row * HH + col);
        }
    }
}

// Masked tiled transpose: fills the vertical-edge segments.
__global__ __launch_bounds__(256)
void sqrl_vert(const float* __restrict__ x, float* __restrict__ out) {
    __shared__ float tile[32][33];
    const int R0 = blockIdx.x * 32;
    const int C0 = blockIdx.y * 32;
    const int bc = blockIdx.z;

    // early-out: does this tile intersect the triangle mask?
    if (C0 >= 256) {
        const int rmax = C0 - 256 + 31;
        if (R0 + 31 < 255 - rmax || R0 > 255 + rmax) return;
    } else {
        const int rmax = 255 - C0;
        if (R0 + 31 < 256 - rmax || R0 > 256 + rmax) return;
    }

    const int tx = threadIdx.x;          // 0..31
    const int ty = threadIdx.y;          // 0..7
    const float* __restrict__ img = x + (size_t)bc * (HH * HH);

    #pragma unroll
    for (int k = 0; k < 4; ++k) {
        const int rowl = ty * 4 + k;
        tile[rowl][tx] = __ldg(img + (R0 + rowl) * HH + C0 + tx);
    }
    __syncthreads();

    float* __restrict__ obase = out + ((size_t)bc * HR) * RL;
    const int row = R0 + tx;

    #pragma unroll
    for (int k = 0; k < 4; ++k) {
        const int u = ty * 4 + k;                  // column offset in tile
        const float v = tile[tx][u];
        if (C0 >= 256) {
            const int r = C0 + u - 256;            // right edge ring
            if (row >= 255 - r && row <= 255 + r)
                obase[(size_t)r * RL + 511 + row] = v;
        } else {
            const int r = 255 - (C0 + u);          // left edge ring
            if (row >= 256 - r && row <= 256 + r)
                obase[(size_t)r * RL + 2044 - row] = v;
        }
    }
}

extern "C" void kernel_launch(void* const* d_in, const int* in_sizes, int n_in,
                              void* d_out, int out_size) {
    const float* x = (const float*)d_in[0];
    float* out = (float*)d_out;
    const int bc = in_sizes[0] / (HH * HH);   // 16*32 = 512 images

    dim3 gA(2, HR, bc);
    sqrl_horiz<<<gA, 256>>>(x, out);

    dim3 gB(16, 16, bc);
    sqrl_vert<<<gB, dim3(32, 8)>>>(x, out);
}